// round 15
// baseline (speedup 1.0000x reference)
#include <cuda_runtime.h>
#include <cuda_fp16.h>
#include <cstdint>

#define HEADS 8
#define SEQ   4096
#define FIN   512
#define HD    64
#define FOUT  512
#define MWORDS (SEQ / 32)              // 128 packed words per mask row

// ---------------------------------------------------------------------------
// Scratch (__device__ globals: allocation-free rule)
// ---------------------------------------------------------------------------
__device__ __half g_Qh[HEADS * SEQ * HD];            // pre-scaled by log2(e)/8
__device__ __half g_Kh[HEADS * SEQ * HD];            // fp16 single
__device__ __half g_Vt[HEADS * HD * SEQ];            // transposed: [h][d][n], fp16
__device__ float g_Hcat[SEQ * (HEADS * HD)];
__device__ uint32_t g_Mpk[HEADS * SEQ * MWORDS];     // bit-packed mask (16 MB)

// ---------------------------------------------------------------------------
// Helpers
// ---------------------------------------------------------------------------
__device__ __forceinline__ uint32_t smem_u32(const void* p) {
    uint32_t a;
    asm("{ .reg .u64 t; cvta.to.shared.u64 t, %1; cvt.u32.u64 %0, t; }"
        : "=r"(a) : "l"(p));
    return a;
}

__device__ __forceinline__ void ldsm_x4(uint32_t r[4], uint32_t addr) {
    asm volatile("ldmatrix.sync.aligned.m8n8.x4.shared.b16 {%0,%1,%2,%3}, [%4];"
                 : "=r"(r[0]), "=r"(r[1]), "=r"(r[2]), "=r"(r[3]) : "r"(addr));
}

__device__ __forceinline__ void mma_f16(float* c, const uint32_t* a, const uint32_t* b) {
    asm volatile(
        "mma.sync.aligned.m16n8k16.row.col.f32.f16.f16.f32 "
        "{%0,%1,%2,%3},{%4,%5,%6,%7},{%8,%9},{%0,%1,%2,%3};"
        : "+f"(c[0]), "+f"(c[1]), "+f"(c[2]), "+f"(c[3])
        : "r"(a[0]), "r"(a[1]), "r"(a[2]), "r"(a[3]), "r"(b[0]), "r"(b[1]));
}

__device__ __forceinline__ uint32_t ex2_h2(uint32_t a) {
    uint32_t r;
    asm("ex2.approx.f16x2 %0, %1;" : "=r"(r) : "r"(a));
    return r;
}

__device__ __forceinline__ uint32_t pack_f16x2(float lo, float hi) {
    __half2 h = __floats2half2_rn(lo, hi);
    return *reinterpret_cast<uint32_t*>(&h);
}
__device__ __forceinline__ float2 unpack_f16x2(uint32_t w) {
    __half2 h = *reinterpret_cast<__half2*>(&w);
    return __half22float2(h);
}

__device__ __forceinline__ void cp16(uint32_t saddr, const void* g) {
    asm volatile("cp.async.cg.shared.global [%0], [%1], 16;"
                 :: "r"(saddr), "l"(g) : "memory");
}
#define CP_COMMIT() asm volatile("cp.async.commit_group;" ::: "memory")
#define CP_WAIT(n)  asm volatile("cp.async.wait_group %0;" :: "n"(n) : "memory")

__device__ __forceinline__ int ldcs1(const int* p) {
    int v;
    asm volatile("ld.global.cs.s32 %0, [%1];" : "=r"(v) : "l"(p));
    return v;
}
__device__ __forceinline__ uint2 ldcs_u2(const uint32_t* p) {
    uint2 v;
    asm volatile("ld.global.cs.v2.u32 {%0,%1}, [%2];"
                 : "=r"(v.x), "=r"(v.y) : "l"(p));
    return v;
}

// B-side split store (hi/lo fp16), 4 values
__device__ __forceinline__ void split_store4(__half* ph, __half* pl, float4 v) {
    uint32_t h0 = pack_f16x2(v.x, v.y);
    uint32_t h1 = pack_f16x2(v.z, v.w);
    float2 f0 = unpack_f16x2(h0);
    float2 f1 = unpack_f16x2(h1);
    uint32_t l0 = pack_f16x2(v.x - f0.x, v.y - f0.y);
    uint32_t l1 = pack_f16x2(v.z - f1.x, v.w - f1.y);
    *(uint2*)ph = make_uint2(h0, h1);
    *(uint2*)pl = make_uint2(l0, l1);
}

// A-side hi-only store, 4 values
__device__ __forceinline__ void hi_store4(__half* ph, float4 v) {
    *(uint2*)ph = make_uint2(pack_f16x2(v.x, v.y), pack_f16x2(v.z, v.w));
}

// ---------------------------------------------------------------------------
// GEMM core (BM=128, BN=64, BK=32, 8 warps, warp tile 32x32)
// A hi-only fp16; B hi/lo fp16; C = A*(Bh+Bl)^T 2-term.
// ---------------------------------------------------------------------------
#define G_LDA 40

#define GEMM_PREFETCH(A_, B_, K_, k0_)                                            \
    do {                                                                          \
        _Pragma("unroll")                                                         \
        for (int it = 0; it < 4; it++) {                                          \
            int i = tid + it * 256;                                               \
            pa[it] = *(const float4*)(A_ + (long)(bm + (i >> 3)) * K_ + (k0_) + (i & 7) * 4); \
        }                                                                         \
        _Pragma("unroll")                                                         \
        for (int it = 0; it < 2; it++) {                                          \
            int i = tid + it * 256;                                               \
            pb[it] = *(const float4*)(B_ + (long)((i >> 3)) * K_ + (k0_) + (i & 7) * 4); \
        }                                                                         \
    } while (0)

#define GEMM_STORE_SMEM()                                                         \
    do {                                                                          \
        _Pragma("unroll")                                                         \
        for (int it = 0; it < 4; it++) {                                          \
            int i = tid + it * 256; int r = i >> 3, c = i & 7;                    \
            hi_store4(Ah + r * G_LDA + c * 4, pa[it]);                            \
        }                                                                         \
        _Pragma("unroll")                                                         \
        for (int it = 0; it < 2; it++) {                                          \
            int i = tid + it * 256; int r = i >> 3, c = i & 7;                    \
            split_store4(Bh + r * G_LDA + c * 4, Bl + r * G_LDA + c * 4, pb[it]); \
        }                                                                         \
    } while (0)

#define GEMM_MMA_BLOCK()                                                          \
    do {                                                                          \
        _Pragma("unroll")                                                         \
        for (int kc = 0; kc < 2; kc++) {                                          \
            uint32_t ah[2][4], bh[2][4], bl[2][4];                                \
            const int ar = wm + (lane & 15);                                      \
            const int acol = kc * 16 + ((lane >> 4) << 3);                        \
            ldsm_x4(ah[0], smem_u32(Ah + ar * G_LDA + acol));                     \
            ldsm_x4(ah[1], smem_u32(Ah + (ar + 16) * G_LDA + acol));              \
            const int brow = ((lane >> 4) << 3) + (lane & 7);                     \
            const int bcol = kc * 16 + (((lane >> 3) & 1) << 3);                  \
            ldsm_x4(bh[0], smem_u32(Bh + (wn + brow) * G_LDA + bcol));            \
            ldsm_x4(bh[1], smem_u32(Bh + (wn + 16 + brow) * G_LDA + bcol));       \
            ldsm_x4(bl[0], smem_u32(Bl + (wn + brow) * G_LDA + bcol));            \
            ldsm_x4(bl[1], smem_u32(Bl + (wn + 16 + brow) * G_LDA + bcol));       \
            _Pragma("unroll")                                                     \
            for (int mi = 0; mi < 2; mi++)                                        \
                _Pragma("unroll")                                                 \
                for (int jp = 0; jp < 2; jp++)                                    \
                    _Pragma("unroll")                                             \
                    for (int u = 0; u < 2; u++) {                                 \
                        int j = jp * 2 + u;                                       \
                        mma_f16(acc[mi][j], ah[mi], &bh[jp][2 * u]);              \
                        mma_f16(acc[mi][j], ah[mi], &bl[jp][2 * u]);              \
                    }                                                             \
        }                                                                         \
    } while (0)

// ---------------------------------------------------------------------------
// Fused projections + mask pack:
// y=0 -> Q fp16 pre-scaled by log2(e)/8;  y=1 -> K fp16;  y=2 -> V^T fp16;
// y=3 -> ballot-pack the mask (DRAM streamer overlapping the MMA CTAs).
// ---------------------------------------------------------------------------
__global__ __launch_bounds__(256) void proj_qkv(
    const float* __restrict__ X,
    const float* __restrict__ W_Q, const float* __restrict__ W_K,
    const float* __restrict__ W_V,
    const int* __restrict__ mask, uint32_t* __restrict__ Mpk,
    __half* __restrict__ Qh_g, __half* __restrict__ Kh_g,
    __half* __restrict__ Vt)
{
    __shared__ __half Ah[128 * G_LDA];
    __shared__ __half Bh[64 * G_LDA], Bl[64 * G_LDA];

    const int tid = threadIdx.x, wid = tid >> 5, lane = tid & 31;
    const int z = blockIdx.z, y = blockIdx.y;

    if (y == 3) {
        // Mask pack branch: 256 CTAs x 8 warps = 2048 warps; 1,048,576 chunks
        const long nchunks = (long)HEADS * SEQ * SEQ / 128;
        const long gw = ((long)z * 32 + blockIdx.x) * 8 + wid;
        const long stride = 256L * 8;
        for (long c = gw; c < nchunks; c += stride) {
            const int* p = mask + c * 128;
            uint32_t w0 = __ballot_sync(0xffffffffu, ldcs1(p + lane)      != 0);
            uint32_t w1 = __ballot_sync(0xffffffffu, ldcs1(p + lane + 32) != 0);
            uint32_t w2 = __ballot_sync(0xffffffffu, ldcs1(p + lane + 64) != 0);
            uint32_t w3 = __ballot_sync(0xffffffffu, ldcs1(p + lane + 96) != 0);
            if (lane == 0)
                *(uint4*)(Mpk + c * 4) = make_uint4(w0, w1, w2, w3);
        }
        return;
    }

    const int bm = blockIdx.x * 128;
    const float* A = X + (long)z * SEQ * FIN;
    const float* B = (y == 0 ? W_Q : (y == 1 ? W_K : W_V)) + (long)z * HD * FIN;
    const int wm = (wid & 3) * 32, wn = (wid >> 2) * 32;

    float acc[2][4][4] = {};
    float4 pa[4], pb[2];
    GEMM_PREFETCH(A, B, FIN, 0);

    for (int k0 = 0; k0 < FIN; k0 += 32) {
        __syncthreads();
        GEMM_STORE_SMEM();
        __syncthreads();
        if (k0 + 32 < FIN) GEMM_PREFETCH(A, B, FIN, k0 + 32);
        GEMM_MMA_BLOCK();
    }

    const float QSC = 0.18033688f;   // log2(e)/8, folded into Q
    #pragma unroll
    for (int mi = 0; mi < 2; mi++) {
        const int gm0 = bm + wm + mi * 16 + (lane >> 2);
        #pragma unroll
        for (int j = 0; j < 4; j++) {
            const int col = wn + j * 8 + (lane & 3) * 2;
            float v0 = acc[mi][j][0], v1 = acc[mi][j][1];
            float v2 = acc[mi][j][2], v3 = acc[mi][j][3];
            if (y == 0) {
                long b0 = ((long)z * SEQ + gm0) * HD + col;
                *(uint32_t*)(Qh_g + b0) = pack_f16x2(v0 * QSC, v1 * QSC);
                *(uint32_t*)(Qh_g + b0 + 8L * HD) = pack_f16x2(v2 * QSC, v3 * QSC);
            } else if (y == 1) {
                long b0 = ((long)z * SEQ + gm0) * HD + col;
                *(uint32_t*)(Kh_g + b0) = pack_f16x2(v0, v1);
                *(uint32_t*)(Kh_g + b0 + 8L * HD) = pack_f16x2(v2, v3);
            } else {
                long t0 = ((long)z * HD + col) * SEQ + gm0;
                Vt[t0]           = __float2half_rn(v0);
                Vt[t0 + SEQ]     = __float2half_rn(v1);
                Vt[t0 + 8]       = __float2half_rn(v2);
                Vt[t0 + SEQ + 8] = __float2half_rn(v3);
            }
        }
    }
}

// ---------------------------------------------------------------------------
// Output projection: out[4096,512] = Hcat[4096,512] * W_O[512,512]^T (fp32)
// ---------------------------------------------------------------------------
__global__ __launch_bounds__(256) void gemm_out(
    const float* __restrict__ A, const float* __restrict__ W,
    float* __restrict__ C)
{
    __shared__ __half Ah[128 * G_LDA];
    __shared__ __half Bh[64 * G_LDA], Bl[64 * G_LDA];

    const int tid = threadIdx.x, wid = tid >> 5, lane = tid & 31;
    const int bm = blockIdx.x * 128, bn = blockIdx.y * 64;
    const float* B = W + (long)bn * FIN;
    const int wm = (wid & 3) * 32, wn = (wid >> 2) * 32;

    float acc[2][4][4] = {};
    float4 pa[4], pb[2];
    GEMM_PREFETCH(A, B, FIN, 0);

    for (int k0 = 0; k0 < FIN; k0 += 32) {
        __syncthreads();
        GEMM_STORE_SMEM();
        __syncthreads();
        if (k0 + 32 < FIN) GEMM_PREFETCH(A, B, FIN, k0 + 32);
        GEMM_MMA_BLOCK();
    }

    #pragma unroll
    for (int mi = 0; mi < 2; mi++) {
        const int gm0 = bm + wm + mi * 16 + (lane >> 2);
        #pragma unroll
        for (int j = 0; j < 4; j++) {
            const int col = bn + wn + j * 8 + (lane & 3) * 2;
            *(float2*)(C + (long)gm0 * FOUT + col) =
                make_float2(acc[mi][j][0], acc[mi][j][1]);
            *(float2*)(C + (long)(gm0 + 8) * FOUT + col) =
                make_float2(acc[mi][j][2], acc[mi][j][3]);
        }
    }
}

// ---------------------------------------------------------------------------
// HMMA flash attention. BQ=128, 128 threads (4 warps, warp M=32 N=64),
// 2 CTAs/SM, single wave. Packed-bit mask (prefetched a tile ahead).
// exp via ex2.approx.f16x2 (halves MUFU pressure); mask applied as a
// bitwise AND on the packed f16 pair.
// ---------------------------------------------------------------------------
#define ATT_LDA 72
#define ROWB    144                    // bytes per smem row
#define HALF_A  9216                   // 64 rows * 144
#define OFF_K   (128 * ROWB)           // after Q (128 rows)
#define OFF_V   (OFF_K + 2 * HALF_A)
#define ATT_SMEM (OFF_V + 2 * HALF_A)  // 55296 bytes

__global__ __launch_bounds__(128, 2) void attn_mma(
    const __half* __restrict__ Qh_g, const __half* __restrict__ Kh_g,
    const __half* __restrict__ Vt, const uint32_t* __restrict__ Mpk,
    float* __restrict__ Hcat)
{
    extern __shared__ char smc[];
    const uint32_t sb = smem_u32(smc);
    __half* Qs = (__half*)smc;

    const int tid = threadIdx.x, wid = tid >> 5, lane = tid & 31;
    const int h = blockIdx.y, q0 = blockIdx.x * 128;
    const long hS = (long)h * SEQ;

    // cp.async mapping: thread (rr, cc): rows rr+16k, 16B chunk cc
    const int rr = (tid >> 3) & 15;   // 0..15
    const int cc = tid & 7;
    const __half* pKh = Kh_g + (hS + rr) * HD + cc * 8;
    const __half* pVh = Vt + ((long)h * HD + rr) * SEQ + cc * 8;
    const uint32_t sKf = sb + OFF_K + rr * ROWB + cc * 16;
    const uint32_t sVf = sb + OFF_V + rr * ROWB + cc * 16;

#define FILL_STAGE(kt_)                                                        \
    do {                                                                       \
        uint32_t k0s = sKf + ((kt_) & 1) * HALF_A;                             \
        uint32_t v0s = sVf + ((kt_) & 1) * HALF_A;                             \
        long ko = (long)(kt_) * 64;                                            \
        _Pragma("unroll")                                                      \
        for (int kq = 0; kq < 4; kq++) {                                       \
            cp16(k0s + kq * 16 * ROWB, pKh + (ko + kq * 16) * HD);             \
            cp16(v0s + kq * 16 * ROWB, pVh + (long)kq * 16 * SEQ + ko);        \
        }                                                                      \
        CP_COMMIT();                                                           \
    } while (0)

    const int r0 = q0 + wid * 32 + (lane >> 2);     // subtile-0 base row
    const int colb = (lane & 3) * 2;
    // packed mask row pointers for rows r0, +8, +16, +24
    const uint32_t* mpA0 = Mpk + (hS + r0) * MWORDS;
    const uint32_t* mpA1 = mpA0 + 8L * MWORDS;
    const uint32_t* mpB0 = mpA0 + 16L * MWORDS;
    const uint32_t* mpB1 = mpA0 + 24L * MWORDS;

    // Current-tile packed mask (64 bits per row)
    uint2 mA0 = ldcs_u2(mpA0), mA1 = ldcs_u2(mpA1);
    uint2 mB0 = ldcs_u2(mpB0), mB1 = ldcs_u2(mpB1);

    // Load Q tile (128 rows, persists all iterations)
    #pragma unroll
    for (int it = 0; it < 8; it++) {
        int i = tid + it * 128;
        int r = i >> 3, c = i & 7;
        *(uint4*)(Qs + r * ATT_LDA + c * 8) =
            *(const uint4*)(Qh_g + (hS + q0 + r) * HD + c * 8);
    }
    FILL_STAGE(0);
    __syncthreads();

    // Q fragments -> registers (2 M-subtiles)
    uint32_t qh[2][4][4];
    #pragma unroll
    for (int mi = 0; mi < 2; mi++) {
        const int r = wid * 32 + mi * 16 + (lane & 15);
        #pragma unroll
        for (int kc = 0; kc < 4; kc++) {
            const int col = kc * 16 + ((lane >> 4) << 3);
            ldsm_x4(qh[mi][kc], smem_u32(Qs + r * ATT_LDA + col));
        }
    }

    float o[2][8][4] = {};
    float lA0 = 0.f, lA1 = 0.f, lB0 = 0.f, lB1 = 0.f;

    for (int kt = 0; kt < SEQ / 64; kt++) {
        if (kt) __syncthreads();
        if (kt + 1 < SEQ / 64) { FILL_STAGE(kt + 1); CP_WAIT(1); }
        else                   { CP_WAIT(0); }
        __syncthreads();

        const uint32_t kbK = sb + OFF_K + (kt & 1) * HALF_A;
        const uint32_t kbV = sb + OFF_V + (kt & 1) * HALF_A;

        // Prefetch NEXT tile's packed mask (tiny; consumed next iteration)
        uint2 nA0, nA1, nB0, nB1;
        const bool more = (kt + 1 < SEQ / 64);
        if (more) {
            nA0 = ldcs_u2(mpA0 + (kt + 1) * 2);
            nA1 = ldcs_u2(mpA1 + (kt + 1) * 2);
            nB0 = ldcs_u2(mpB0 + (kt + 1) * 2);
            nB1 = ldcs_u2(mpB1 + (kt + 1) * 2);
        }

        // S = Qh * Kh; each K fragment feeds both M-subtiles
        float s[2][8][4] = {};
        const int brow = ((lane >> 4) << 3) + (lane & 7);
        #pragma unroll
        for (int kc = 0; kc < 4; kc++) {
            uint32_t kbh[4][4];
            const int bcol = (kc * 16 + (((lane >> 3) & 1) << 3)) * 2;
            #pragma unroll
            for (int jp = 0; jp < 4; jp++)
                ldsm_x4(kbh[jp], kbK + (jp * 16 + brow) * ROWB + bcol);
            #pragma unroll
            for (int jp = 0; jp < 4; jp++) {
                mma_f16(s[0][2 * jp],     qh[0][kc], &kbh[jp][0]);
                mma_f16(s[0][2 * jp + 1], qh[0][kc], &kbh[jp][2]);
                mma_f16(s[1][2 * jp],     qh[1][kc], &kbh[jp][0]);
                mma_f16(s[1][2 * jp + 1], qh[1][kc], &kbh[jp][2]);
            }
        }

        // exp via f16x2 MUFU, mask via bitwise AND; l accumulated in f32.
        // P fragments produced directly in packed form.
        uint32_t ph[2][4][4];
        #pragma unroll
        for (int j = 0; j < 8; j++) {
            const int sh = 8 * (j & 3) + colb;
            const uint32_t wA0 = (j < 4) ? mA0.x : mA0.y;
            const uint32_t wA1 = (j < 4) ? mA1.x : mA1.y;
            const uint32_t wB0 = (j < 4) ? mB0.x : mB0.y;
            const uint32_t wB1 = (j < 4) ? mB1.x : mB1.y;
            const int kc = j >> 1, u = j & 1;

            uint32_t p01 = ex2_h2(pack_f16x2(s[0][j][0], s[0][j][1]));
            uint32_t p23 = ex2_h2(pack_f16x2(s[0][j][2], s[0][j][3]));
            uint32_t bA0 = (wA0 >> sh) & 3u;
            uint32_t bA1 = (wA1 >> sh) & 3u;
            p01 &= ((bA0 & 1u) * 0xFFFFu) | ((bA0 >> 1) * 0xFFFF0000u);
            p23 &= ((bA1 & 1u) * 0xFFFFu) | ((bA1 >> 1) * 0xFFFF0000u);
            float2 f01 = unpack_f16x2(p01);
            float2 f23 = unpack_f16x2(p23);
            lA0 += f01.x + f01.y;
            lA1 += f23.x + f23.y;
            ph[0][kc][2 * u]     = p01;
            ph[0][kc][2 * u + 1] = p23;

            uint32_t q01 = ex2_h2(pack_f16x2(s[1][j][0], s[1][j][1]));
            uint32_t q23 = ex2_h2(pack_f16x2(s[1][j][2], s[1][j][3]));
            uint32_t bB0 = (wB0 >> sh) & 3u;
            uint32_t bB1 = (wB1 >> sh) & 3u;
            q01 &= ((bB0 & 1u) * 0xFFFFu) | ((bB0 >> 1) * 0xFFFF0000u);
            q23 &= ((bB1 & 1u) * 0xFFFFu) | ((bB1 >> 1) * 0xFFFF0000u);
            float2 g01 = unpack_f16x2(q01);
            float2 g23 = unpack_f16x2(q23);
            lB0 += g01.x + g01.y;
            lB1 += g23.x + g23.y;
            ph[1][kc][2 * u]     = q01;
            ph[1][kc][2 * u + 1] = q23;
        }

        // O += Ph * Vh; each V fragment feeds both subtiles
        #pragma unroll
        for (int kc = 0; kc < 4; kc++) {
            uint32_t vbh[4][4];
            const int bcol = (kc * 16 + (((lane >> 3) & 1) << 3)) * 2;
            #pragma unroll
            for (int jp = 0; jp < 4; jp++)
                ldsm_x4(vbh[jp], kbV + (jp * 16 + brow) * ROWB + bcol);
            #pragma unroll
            for (int jp = 0; jp < 4; jp++) {
                mma_f16(o[0][2 * jp],     ph[0][kc], &vbh[jp][0]);
                mma_f16(o[0][2 * jp + 1], ph[0][kc], &vbh[jp][2]);
                mma_f16(o[1][2 * jp],     ph[1][kc], &vbh[jp][0]);
                mma_f16(o[1][2 * jp + 1], ph[1][kc], &vbh[jp][2]);
            }
        }

        // rotate mask prefetch
        if (more) { mA0 = nA0; mA1 = nA1; mB0 = nB0; mB1 = nB1; }
    }

    // Quad reduce l, normalize, write Hcat
    lA0 += __shfl_xor_sync(0xffffffffu, lA0, 1);
    lA0 += __shfl_xor_sync(0xffffffffu, lA0, 2);
    lA1 += __shfl_xor_sync(0xffffffffu, lA1, 1);
    lA1 += __shfl_xor_sync(0xffffffffu, lA1, 2);
    lB0 += __shfl_xor_sync(0xffffffffu, lB0, 1);
    lB0 += __shfl_xor_sync(0xffffffffu, lB0, 2);
    lB1 += __shfl_xor_sync(0xffffffffu, lB1, 1);
    lB1 += __shfl_xor_sync(0xffffffffu, lB1, 2);
    const float iA0 = 1.f / lA0, iA1 = 1.f / lA1;
    const float iB0 = 1.f / lB0, iB1 = 1.f / lB1;
    #pragma unroll
    for (int j = 0; j < 8; j++) {
        const int colg = h * HD + j * 8 + colb;
        *(float2*)(Hcat + (long)r0 * (HEADS * HD) + colg) =
            make_float2(o[0][j][0] * iA0, o[0][j][1] * iA0);
        *(float2*)(Hcat + (long)(r0 + 8) * (HEADS * HD) + colg) =
            make_float2(o[0][j][2] * iA1, o[0][j][3] * iA1);
        *(float2*)(Hcat + (long)(r0 + 16) * (HEADS * HD) + colg) =
            make_float2(o[1][j][0] * iB0, o[1][j][1] * iB0);
        *(float2*)(Hcat + (long)(r0 + 24) * (HEADS * HD) + colg) =
            make_float2(o[1][j][2] * iB1, o[1][j][3] * iB1);
    }
}

// ---------------------------------------------------------------------------
extern "C" void kernel_launch(void* const* d_in, const int* in_sizes, int n_in,
                              void* d_out, int out_size)
{
    const float* X    = (const float*)d_in[0];
    const int*   mask = (const int*)  d_in[1];
    const float* W_Q  = (const float*)d_in[2];
    const float* W_K  = (const float*)d_in[3];
    const float* W_V  = (const float*)d_in[4];
    const float* W_O  = (const float*)d_in[5];
    float* out = (float*)d_out;

    __half *Qh_g, *Kh_g, *Vt;
    float* Hc;
    uint32_t* Mpk;
    cudaGetSymbolAddress((void**)&Qh_g, g_Qh);
    cudaGetSymbolAddress((void**)&Kh_g, g_Kh);
    cudaGetSymbolAddress((void**)&Vt,   g_Vt);
    cudaGetSymbolAddress((void**)&Hc,   g_Hcat);
    cudaGetSymbolAddress((void**)&Mpk,  g_Mpk);

    // Fused Q/K/V projections + mask bit-pack (y=3 CTAs stream the mask)
    dim3 gProj(SEQ / 128, 4, HEADS);
    proj_qkv<<<gProj, 256>>>(X, W_Q, W_K, W_V, mask, Mpk, Qh_g, Kh_g, Vt);

    // Attention (BQ=128, packed mask, f16x2 exp, single wave)
    cudaFuncSetAttribute(attn_mma,
                         cudaFuncAttributeMaxDynamicSharedMemorySize, ATT_SMEM);
    dim3 gAttn(SEQ / 128, HEADS);
    attn_mma<<<gAttn, 128, ATT_SMEM>>>(Qh_g, Kh_g, Vt, Mpk, Hc);

    // Output projection
    dim3 gOut(SEQ / 128, FOUT / 64);
    gemm_out<<<gOut, 256>>>(Hc, W_O, out);
}

// round 16
// speedup vs baseline: 2.7362x; 2.7362x over previous
#include <cuda_runtime.h>
#include <cuda_fp16.h>
#include <cstdint>

#define HEADS 8
#define SEQ   4096
#define FIN   512
#define HD    64
#define FOUT  512

// ---------------------------------------------------------------------------
// Scratch (__device__ globals: allocation-free rule)
// ---------------------------------------------------------------------------
__device__ __half g_Qh[HEADS * SEQ * HD];            // pre-scaled by log2(e)/8
__device__ __half g_Kh[HEADS * SEQ * HD];            // fp16 single
__device__ __half g_Vt[HEADS * HD * SEQ];            // transposed: [h][d][n], fp16
__device__ float g_Hcat[SEQ * (HEADS * HD)];

// ---------------------------------------------------------------------------
// Helpers
// ---------------------------------------------------------------------------
__device__ __forceinline__ uint32_t smem_u32(const void* p) {
    uint32_t a;
    asm("{ .reg .u64 t; cvta.to.shared.u64 t, %1; cvt.u32.u64 %0, t; }"
        : "=r"(a) : "l"(p));
    return a;
}

__device__ __forceinline__ void ldsm_x4(uint32_t r[4], uint32_t addr) {
    asm volatile("ldmatrix.sync.aligned.m8n8.x4.shared.b16 {%0,%1,%2,%3}, [%4];"
                 : "=r"(r[0]), "=r"(r[1]), "=r"(r[2]), "=r"(r[3]) : "r"(addr));
}

__device__ __forceinline__ void mma_f16(float* c, const uint32_t* a, const uint32_t* b) {
    asm volatile(
        "mma.sync.aligned.m16n8k16.row.col.f32.f16.f16.f32 "
        "{%0,%1,%2,%3},{%4,%5,%6,%7},{%8,%9},{%0,%1,%2,%3};"
        : "+f"(c[0]), "+f"(c[1]), "+f"(c[2]), "+f"(c[3])
        : "r"(a[0]), "r"(a[1]), "r"(a[2]), "r"(a[3]), "r"(b[0]), "r"(b[1]));
}

__device__ __forceinline__ uint32_t ex2_h2(uint32_t a) {
    uint32_t r;
    asm("ex2.approx.f16x2 %0, %1;" : "=r"(r) : "r"(a));
    return r;
}

__device__ __forceinline__ uint32_t pack_f16x2(float lo, float hi) {
    __half2 h = __floats2half2_rn(lo, hi);
    return *reinterpret_cast<uint32_t*>(&h);
}
__device__ __forceinline__ float2 unpack_f16x2(uint32_t w) {
    __half2 h = *reinterpret_cast<__half2*>(&w);
    return __half22float2(h);
}

__device__ __forceinline__ void cp16(uint32_t saddr, const void* g) {
    asm volatile("cp.async.cg.shared.global [%0], [%1], 16;"
                 :: "r"(saddr), "l"(g) : "memory");
}
#define CP_COMMIT() asm volatile("cp.async.commit_group;" ::: "memory")
#define CP_WAIT(n)  asm volatile("cp.async.wait_group %0;" :: "n"(n) : "memory")

// streaming (evict-first) int2 load for the one-pass mask stream
__device__ __forceinline__ int2 ldcs2(const int* p) {
    int2 v;
    asm volatile("ld.global.cs.v2.s32 {%0,%1}, [%2];"
                 : "=r"(v.x), "=r"(v.y) : "l"(p));
    return v;
}

// B-side split store (hi/lo fp16), 4 values
__device__ __forceinline__ void split_store4(__half* ph, __half* pl, float4 v) {
    uint32_t h0 = pack_f16x2(v.x, v.y);
    uint32_t h1 = pack_f16x2(v.z, v.w);
    float2 f0 = unpack_f16x2(h0);
    float2 f1 = unpack_f16x2(h1);
    uint32_t l0 = pack_f16x2(v.x - f0.x, v.y - f0.y);
    uint32_t l1 = pack_f16x2(v.z - f1.x, v.w - f1.y);
    *(uint2*)ph = make_uint2(h0, h1);
    *(uint2*)pl = make_uint2(l0, l1);
}

// A-side hi-only store, 4 values
__device__ __forceinline__ void hi_store4(__half* ph, float4 v) {
    *(uint2*)ph = make_uint2(pack_f16x2(v.x, v.y), pack_f16x2(v.z, v.w));
}

// ---------------------------------------------------------------------------
// GEMM core (BM=128, BN=64, BK=32, 8 warps, warp tile 32x32)
// A hi-only fp16; B hi/lo fp16; C = A*(Bh+Bl)^T 2-term.
// ---------------------------------------------------------------------------
#define G_LDA 40

#define GEMM_PREFETCH(A_, B_, K_, k0_)                                            \
    do {                                                                          \
        _Pragma("unroll")                                                         \
        for (int it = 0; it < 4; it++) {                                          \
            int i = tid + it * 256;                                               \
            pa[it] = *(const float4*)(A_ + (long)(bm + (i >> 3)) * K_ + (k0_) + (i & 7) * 4); \
        }                                                                         \
        _Pragma("unroll")                                                         \
        for (int it = 0; it < 2; it++) {                                          \
            int i = tid + it * 256;                                               \
            pb[it] = *(const float4*)(B_ + (long)((i >> 3)) * K_ + (k0_) + (i & 7) * 4); \
        }                                                                         \
    } while (0)

#define GEMM_STORE_SMEM()                                                         \
    do {                                                                          \
        _Pragma("unroll")                                                         \
        for (int it = 0; it < 4; it++) {                                          \
            int i = tid + it * 256; int r = i >> 3, c = i & 7;                    \
            hi_store4(Ah + r * G_LDA + c * 4, pa[it]);                            \
        }                                                                         \
        _Pragma("unroll")                                                         \
        for (int it = 0; it < 2; it++) {                                          \
            int i = tid + it * 256; int r = i >> 3, c = i & 7;                    \
            split_store4(Bh + r * G_LDA + c * 4, Bl + r * G_LDA + c * 4, pb[it]); \
        }                                                                         \
    } while (0)

#define GEMM_MMA_BLOCK()                                                          \
    do {                                                                          \
        _Pragma("unroll")                                                         \
        for (int kc = 0; kc < 2; kc++) {                                          \
            uint32_t ah[2][4], bh[2][4], bl[2][4];                                \
            const int ar = wm + (lane & 15);                                      \
            const int acol = kc * 16 + ((lane >> 4) << 3);                        \
            ldsm_x4(ah[0], smem_u32(Ah + ar * G_LDA + acol));                     \
            ldsm_x4(ah[1], smem_u32(Ah + (ar + 16) * G_LDA + acol));              \
            const int brow = ((lane >> 4) << 3) + (lane & 7);                     \
            const int bcol = kc * 16 + (((lane >> 3) & 1) << 3);                  \
            ldsm_x4(bh[0], smem_u32(Bh + (wn + brow) * G_LDA + bcol));            \
            ldsm_x4(bh[1], smem_u32(Bh + (wn + 16 + brow) * G_LDA + bcol));       \
            ldsm_x4(bl[0], smem_u32(Bl + (wn + brow) * G_LDA + bcol));            \
            ldsm_x4(bl[1], smem_u32(Bl + (wn + 16 + brow) * G_LDA + bcol));       \
            _Pragma("unroll")                                                     \
            for (int mi = 0; mi < 2; mi++)                                        \
                _Pragma("unroll")                                                 \
                for (int jp = 0; jp < 2; jp++)                                    \
                    _Pragma("unroll")                                             \
                    for (int u = 0; u < 2; u++) {                                 \
                        int j = jp * 2 + u;                                       \
                        mma_f16(acc[mi][j], ah[mi], &bh[jp][2 * u]);              \
                        mma_f16(acc[mi][j], ah[mi], &bl[jp][2 * u]);              \
                    }                                                             \
        }                                                                         \
    } while (0)

// ---------------------------------------------------------------------------
// Fused Q/K/V projection:
// y=0 -> Q fp16 pre-scaled by log2(e)/8;  y=1 -> K fp16;  y=2 -> V^T fp16
// ---------------------------------------------------------------------------
__global__ __launch_bounds__(256) void proj_qkv(
    const float* __restrict__ X,
    const float* __restrict__ W_Q, const float* __restrict__ W_K,
    const float* __restrict__ W_V,
    __half* __restrict__ Qh_g, __half* __restrict__ Kh_g,
    __half* __restrict__ Vt)
{
    __shared__ __half Ah[128 * G_LDA];
    __shared__ __half Bh[64 * G_LDA], Bl[64 * G_LDA];

    const int tid = threadIdx.x, wid = tid >> 5, lane = tid & 31;
    const int z = blockIdx.z, y = blockIdx.y;
    const int bm = blockIdx.x * 128;
    const float* A = X + (long)z * SEQ * FIN;
    const float* B = (y == 0 ? W_Q : (y == 1 ? W_K : W_V)) + (long)z * HD * FIN;
    const int wm = (wid & 3) * 32, wn = (wid >> 2) * 32;

    float acc[2][4][4] = {};
    float4 pa[4], pb[2];
    GEMM_PREFETCH(A, B, FIN, 0);

    for (int k0 = 0; k0 < FIN; k0 += 32) {
        __syncthreads();
        GEMM_STORE_SMEM();
        __syncthreads();
        if (k0 + 32 < FIN) GEMM_PREFETCH(A, B, FIN, k0 + 32);
        GEMM_MMA_BLOCK();
    }

    const float QSC = 0.18033688f;   // log2(e)/8, folded into Q
    #pragma unroll
    for (int mi = 0; mi < 2; mi++) {
        const int gm0 = bm + wm + mi * 16 + (lane >> 2);
        #pragma unroll
        for (int j = 0; j < 4; j++) {
            const int col = wn + j * 8 + (lane & 3) * 2;
            float v0 = acc[mi][j][0], v1 = acc[mi][j][1];
            float v2 = acc[mi][j][2], v3 = acc[mi][j][3];
            if (y == 0) {
                long b0 = ((long)z * SEQ + gm0) * HD + col;
                *(uint32_t*)(Qh_g + b0) = pack_f16x2(v0 * QSC, v1 * QSC);
                *(uint32_t*)(Qh_g + b0 + 8L * HD) = pack_f16x2(v2 * QSC, v3 * QSC);
            } else if (y == 1) {
                long b0 = ((long)z * SEQ + gm0) * HD + col;
                *(uint32_t*)(Kh_g + b0) = pack_f16x2(v0, v1);
                *(uint32_t*)(Kh_g + b0 + 8L * HD) = pack_f16x2(v2, v3);
            } else {
                long t0 = ((long)z * HD + col) * SEQ + gm0;
                Vt[t0]           = __float2half_rn(v0);
                Vt[t0 + SEQ]     = __float2half_rn(v1);
                Vt[t0 + 8]       = __float2half_rn(v2);
                Vt[t0 + SEQ + 8] = __float2half_rn(v3);
            }
        }
    }
}

// ---------------------------------------------------------------------------
// Output projection: out[4096,512] = Hcat[4096,512] * W_O[512,512]^T (fp32)
// ---------------------------------------------------------------------------
__global__ __launch_bounds__(256) void gemm_out(
    const float* __restrict__ A, const float* __restrict__ W,
    float* __restrict__ C)
{
    __shared__ __half Ah[128 * G_LDA];
    __shared__ __half Bh[64 * G_LDA], Bl[64 * G_LDA];

    const int tid = threadIdx.x, wid = tid >> 5, lane = tid & 31;
    const int bm = blockIdx.x * 128, bn = blockIdx.y * 64;
    const float* B = W + (long)bn * FIN;
    const int wm = (wid & 3) * 32, wn = (wid >> 2) * 32;

    float acc[2][4][4] = {};
    float4 pa[4], pb[2];
    GEMM_PREFETCH(A, B, FIN, 0);

    for (int k0 = 0; k0 < FIN; k0 += 32) {
        __syncthreads();
        GEMM_STORE_SMEM();
        __syncthreads();
        if (k0 + 32 < FIN) GEMM_PREFETCH(A, B, FIN, k0 + 32);
        GEMM_MMA_BLOCK();
    }

    #pragma unroll
    for (int mi = 0; mi < 2; mi++) {
        const int gm0 = bm + wm + mi * 16 + (lane >> 2);
        #pragma unroll
        for (int j = 0; j < 4; j++) {
            const int col = bn + wn + j * 8 + (lane & 3) * 2;
            *(float2*)(C + (long)gm0 * FOUT + col) =
                make_float2(acc[mi][j][0], acc[mi][j][1]);
            *(float2*)(C + (long)(gm0 + 8) * FOUT + col) =
                make_float2(acc[mi][j][2], acc[mi][j][3]);
        }
    }
}

// ---------------------------------------------------------------------------
// HMMA flash attention (R12 structure). BQ=128, 128 threads (4 warps,
// warp M=32 N=64), 2 CTAs/SM, single wave. Inline mask stream, prefetched
// one tile ahead and packed to 2x uint32 bitmasks at end of iteration.
// exp via ex2.approx.f16x2 (halves MUFU); mask applied as bitwise AND.
// ---------------------------------------------------------------------------
#define ATT_LDA 72
#define ROWB    144                    // bytes per smem row
#define HALF_A  9216                   // 64 rows * 144
#define OFF_K   (128 * ROWB)           // after Q (128 rows)
#define OFF_V   (OFF_K + 2 * HALF_A)
#define ATT_SMEM (OFF_V + 2 * HALF_A)  // 55296 bytes

__global__ __launch_bounds__(128, 2) void attn_mma(
    const __half* __restrict__ Qh_g, const __half* __restrict__ Kh_g,
    const __half* __restrict__ Vt,
    const int* __restrict__ mask, float* __restrict__ Hcat)
{
    extern __shared__ char smc[];
    const uint32_t sb = smem_u32(smc);
    __half* Qs = (__half*)smc;

    const int tid = threadIdx.x, wid = tid >> 5, lane = tid & 31;
    const int h = blockIdx.y, q0 = blockIdx.x * 128;
    const long hS = (long)h * SEQ;

    // cp.async mapping: thread (rr, cc): rows rr+16k, 16B chunk cc
    const int rr = (tid >> 3) & 15;   // 0..15
    const int cc = tid & 7;
    const __half* pKh = Kh_g + (hS + rr) * HD + cc * 8;
    const __half* pVh = Vt + ((long)h * HD + rr) * SEQ + cc * 8;
    const uint32_t sKf = sb + OFF_K + rr * ROWB + cc * 16;
    const uint32_t sVf = sb + OFF_V + rr * ROWB + cc * 16;

#define FILL_STAGE(kt_)                                                        \
    do {                                                                       \
        uint32_t k0s = sKf + ((kt_) & 1) * HALF_A;                             \
        uint32_t v0s = sVf + ((kt_) & 1) * HALF_A;                             \
        long ko = (long)(kt_) * 64;                                            \
        _Pragma("unroll")                                                      \
        for (int kq = 0; kq < 4; kq++) {                                       \
            cp16(k0s + kq * 16 * ROWB, pKh + (ko + kq * 16) * HD);             \
            cp16(v0s + kq * 16 * ROWB, pVh + (long)kq * 16 * SEQ + ko);        \
        }                                                                      \
        CP_COMMIT();                                                           \
    } while (0)

    const int r0 = q0 + wid * 32 + (lane >> 2);     // subtile-0 base row
    const int colb = (lane & 3) * 2;
    const int* mrow0 = mask + (hS + r0) * SEQ;      // rows r0, +8, +16, +24

    // Initial mask (tile 0): load and pack (startup; overlapped with fills)
    uint32_t mcA = 0, mcB = 0;
    {
        #pragma unroll
        for (int j = 0; j < 8; j++) {
            int2 t0 = ldcs2(mrow0 + j * 8 + colb);
            int2 t1 = ldcs2(mrow0 + 8L * SEQ + j * 8 + colb);
            int2 t2 = ldcs2(mrow0 + 16L * SEQ + j * 8 + colb);
            int2 t3 = ldcs2(mrow0 + 24L * SEQ + j * 8 + colb);
            mcA |= ((uint32_t)t0.x << (4 * j))     | ((uint32_t)t0.y << (4 * j + 1))
                 | ((uint32_t)t1.x << (4 * j + 2)) | ((uint32_t)t1.y << (4 * j + 3));
            mcB |= ((uint32_t)t2.x << (4 * j))     | ((uint32_t)t2.y << (4 * j + 1))
                 | ((uint32_t)t3.x << (4 * j + 2)) | ((uint32_t)t3.y << (4 * j + 3));
        }
    }

    // Load Q tile (128 rows, persists all iterations)
    #pragma unroll
    for (int it = 0; it < 8; it++) {
        int i = tid + it * 128;
        int r = i >> 3, c = i & 7;
        *(uint4*)(Qs + r * ATT_LDA + c * 8) =
            *(const uint4*)(Qh_g + (hS + q0 + r) * HD + c * 8);
    }
    FILL_STAGE(0);
    __syncthreads();

    // Q fragments -> registers (2 M-subtiles)
    uint32_t qh[2][4][4];
    #pragma unroll
    for (int mi = 0; mi < 2; mi++) {
        const int r = wid * 32 + mi * 16 + (lane & 15);
        #pragma unroll
        for (int kc = 0; kc < 4; kc++) {
            const int col = kc * 16 + ((lane >> 4) << 3);
            ldsm_x4(qh[mi][kc], smem_u32(Qs + r * ATT_LDA + col));
        }
    }

    float o[2][8][4] = {};
    float lA0 = 0.f, lA1 = 0.f, lB0 = 0.f, lB1 = 0.f;

    for (int kt = 0; kt < SEQ / 64; kt++) {
        if (kt) __syncthreads();
        if (kt + 1 < SEQ / 64) { FILL_STAGE(kt + 1); CP_WAIT(1); }
        else                   { CP_WAIT(0); }
        __syncthreads();

        const uint32_t kbK = sb + OFF_K + (kt & 1) * HALF_A;
        const uint32_t kbV = sb + OFF_V + (kt & 1) * HALF_A;

        // Issue NEXT tile's mask loads (packed at end of iteration)
        int2 t0[8], t1[8], t2[8], t3[8];
        const bool more = (kt + 1 < SEQ / 64);
        if (more) {
            const int* mb = mrow0 + (kt + 1) * 64;
            #pragma unroll
            for (int j = 0; j < 8; j++) {
                t0[j] = ldcs2(mb + j * 8 + colb);
                t1[j] = ldcs2(mb + 8L * SEQ + j * 8 + colb);
                t2[j] = ldcs2(mb + 16L * SEQ + j * 8 + colb);
                t3[j] = ldcs2(mb + 24L * SEQ + j * 8 + colb);
            }
        }

        // S = Qh * Kh; each K fragment feeds both M-subtiles
        float s[2][8][4] = {};
        const int brow = ((lane >> 4) << 3) + (lane & 7);
        #pragma unroll
        for (int kc = 0; kc < 4; kc++) {
            uint32_t kbh[4][4];
            const int bcol = (kc * 16 + (((lane >> 3) & 1) << 3)) * 2;
            #pragma unroll
            for (int jp = 0; jp < 4; jp++)
                ldsm_x4(kbh[jp], kbK + (jp * 16 + brow) * ROWB + bcol);
            #pragma unroll
            for (int jp = 0; jp < 4; jp++) {
                mma_f16(s[0][2 * jp],     qh[0][kc], &kbh[jp][0]);
                mma_f16(s[0][2 * jp + 1], qh[0][kc], &kbh[jp][2]);
                mma_f16(s[1][2 * jp],     qh[1][kc], &kbh[jp][0]);
                mma_f16(s[1][2 * jp + 1], qh[1][kc], &kbh[jp][2]);
            }
        }

        // exp via f16x2 MUFU, mask via bitwise AND on packed pair;
        // P fragments produced directly in packed form; l in f32.
        uint32_t ph[2][4][4];
        #pragma unroll
        for (int j = 0; j < 8; j++) {
            const int kc = j >> 1, u = j & 1;
            const uint32_t bA = mcA >> (4 * j);
            const uint32_t bB = mcB >> (4 * j);

            uint32_t p01 = ex2_h2(pack_f16x2(s[0][j][0], s[0][j][1]));
            uint32_t p23 = ex2_h2(pack_f16x2(s[0][j][2], s[0][j][3]));
            p01 &= ((bA & 1u) * 0xFFFFu) | (((bA >> 1) & 1u) * 0xFFFF0000u);
            p23 &= (((bA >> 2) & 1u) * 0xFFFFu) | (((bA >> 3) & 1u) * 0xFFFF0000u);
            float2 f01 = unpack_f16x2(p01);
            float2 f23 = unpack_f16x2(p23);
            lA0 += f01.x + f01.y;
            lA1 += f23.x + f23.y;
            ph[0][kc][2 * u]     = p01;
            ph[0][kc][2 * u + 1] = p23;

            uint32_t q01 = ex2_h2(pack_f16x2(s[1][j][0], s[1][j][1]));
            uint32_t q23 = ex2_h2(pack_f16x2(s[1][j][2], s[1][j][3]));
            q01 &= ((bB & 1u) * 0xFFFFu) | (((bB >> 1) & 1u) * 0xFFFF0000u);
            q23 &= (((bB >> 2) & 1u) * 0xFFFFu) | (((bB >> 3) & 1u) * 0xFFFF0000u);
            float2 g01 = unpack_f16x2(q01);
            float2 g23 = unpack_f16x2(q23);
            lB0 += g01.x + g01.y;
            lB1 += g23.x + g23.y;
            ph[1][kc][2 * u]     = q01;
            ph[1][kc][2 * u + 1] = q23;
        }

        // O += Ph * Vh; each V fragment feeds both subtiles
        #pragma unroll
        for (int kc = 0; kc < 4; kc++) {
            uint32_t vbh[4][4];
            const int bcol = (kc * 16 + (((lane >> 3) & 1) << 3)) * 2;
            #pragma unroll
            for (int jp = 0; jp < 4; jp++)
                ldsm_x4(vbh[jp], kbV + (jp * 16 + brow) * ROWB + bcol);
            #pragma unroll
            for (int jp = 0; jp < 4; jp++) {
                mma_f16(o[0][2 * jp],     ph[0][kc], &vbh[jp][0]);
                mma_f16(o[0][2 * jp + 1], ph[0][kc], &vbh[jp][2]);
                mma_f16(o[1][2 * jp],     ph[1][kc], &vbh[jp][0]);
                mma_f16(o[1][2 * jp + 1], ph[1][kc], &vbh[jp][2]);
            }
        }

        // Pack next-tile mask (loads have had the whole iteration to land)
        if (more) {
            uint32_t a = 0, b = 0;
            #pragma unroll
            for (int j = 0; j < 8; j++) {
                a |= ((uint32_t)t0[j].x << (4 * j))     | ((uint32_t)t0[j].y << (4 * j + 1))
                   | ((uint32_t)t1[j].x << (4 * j + 2)) | ((uint32_t)t1[j].y << (4 * j + 3));
                b |= ((uint32_t)t2[j].x << (4 * j))     | ((uint32_t)t2[j].y << (4 * j + 1))
                   | ((uint32_t)t3[j].x << (4 * j + 2)) | ((uint32_t)t3[j].y << (4 * j + 3));
            }
            mcA = a; mcB = b;
        }
    }

    // Quad reduce l, normalize, write Hcat
    lA0 += __shfl_xor_sync(0xffffffffu, lA0, 1);
    lA0 += __shfl_xor_sync(0xffffffffu, lA0, 2);
    lA1 += __shfl_xor_sync(0xffffffffu, lA1, 1);
    lA1 += __shfl_xor_sync(0xffffffffu, lA1, 2);
    lB0 += __shfl_xor_sync(0xffffffffu, lB0, 1);
    lB0 += __shfl_xor_sync(0xffffffffu, lB0, 2);
    lB1 += __shfl_xor_sync(0xffffffffu, lB1, 1);
    lB1 += __shfl_xor_sync(0xffffffffu, lB1, 2);
    const float iA0 = 1.f / lA0, iA1 = 1.f / lA1;
    const float iB0 = 1.f / lB0, iB1 = 1.f / lB1;
    #pragma unroll
    for (int j = 0; j < 8; j++) {
        const int colg = h * HD + j * 8 + colb;
        *(float2*)(Hcat + (long)r0 * (HEADS * HD) + colg) =
            make_float2(o[0][j][0] * iA0, o[0][j][1] * iA0);
        *(float2*)(Hcat + (long)(r0 + 8) * (HEADS * HD) + colg) =
            make_float2(o[0][j][2] * iA1, o[0][j][3] * iA1);
        *(float2*)(Hcat + (long)(r0 + 16) * (HEADS * HD) + colg) =
            make_float2(o[1][j][0] * iB0, o[1][j][1] * iB0);
        *(float2*)(Hcat + (long)(r0 + 24) * (HEADS * HD) + colg) =
            make_float2(o[1][j][2] * iB1, o[1][j][3] * iB1);
    }
}

// ---------------------------------------------------------------------------
extern "C" void kernel_launch(void* const* d_in, const int* in_sizes, int n_in,
                              void* d_out, int out_size)
{
    const float* X    = (const float*)d_in[0];
    const int*   mask = (const int*)  d_in[1];
    const float* W_Q  = (const float*)d_in[2];
    const float* W_K  = (const float*)d_in[3];
    const float* W_V  = (const float*)d_in[4];
    const float* W_O  = (const float*)d_in[5];
    float* out = (float*)d_out;

    __half *Qh_g, *Kh_g, *Vt;
    float* Hc;
    cudaGetSymbolAddress((void**)&Qh_g, g_Qh);
    cudaGetSymbolAddress((void**)&Kh_g, g_Kh);
    cudaGetSymbolAddress((void**)&Vt,   g_Vt);
    cudaGetSymbolAddress((void**)&Hc,   g_Hcat);

    // Fused Q/K/V projections
    dim3 gProj(SEQ / 128, 3, HEADS);
    proj_qkv<<<gProj, 256>>>(X, W_Q, W_K, W_V, Qh_g, Kh_g, Vt);

    // Attention (BQ=128, inline mask, f16x2 exp, single wave)
    cudaFuncSetAttribute(attn_mma,
                         cudaFuncAttributeMaxDynamicSharedMemorySize, ATT_SMEM);
    dim3 gAttn(SEQ / 128, HEADS);
    attn_mma<<<gAttn, 128, ATT_SMEM>>>(Qh_g, Kh_g, Vt, mask, Hc);

    // Output projection
    dim3 gOut(SEQ / 128, FOUT / 64);
    gemm_out<<<gOut, 256>>>(Hc, W_O, out);
}